// round 6
// baseline (speedup 1.0000x reference)
#include <cuda_runtime.h>
#include <cuda_bf16.h>
#include <math.h>

#define Bb 4
#define Ss 4096
#define Hh 8
#define Dd 64
#define HD 512
#define NC 64
#define CS 64
#define BSn 16384
#define Mm 131072          // B*S*H rows
#define MD (Mm*64)         // 8.39M elems

// ---- fp32 scratch ----
__device__ float g_fg  [MD];
__device__ float g_igh [MD];
__device__ float g_ctot[Bb*NC*HD];
__device__ float g_a   [Bb*NC*HD];
__device__ float g_bv  [Bb*NC*HD];
__device__ int   g_flag[Bb*NC];
// ---- bf16 hi/lo operand scratch ----
__device__ __nv_bfloat16 g_xh[MD], g_xl[MD];
__device__ __nv_bfloat16 g_lnh[MD], g_lnl[MD];
__device__ __nv_bfloat16 g_ch[MD], g_cl[MD];
__device__ __nv_bfloat16 g_W1h[192*128], g_W1l[192*128];   // [c][k], gate-remapped
__device__ __nv_bfloat16 g_W2h[64*128],  g_W2l[64*128];    // [n][k]

__device__ __forceinline__ float sigmf(float z){ return 1.f/(1.f+__expf(-z)); }

__device__ __forceinline__ void split_bf16(float v, __nv_bfloat16 &h, __nv_bfloat16 &l){
    h = __float2bfloat16(v);
    l = __float2bfloat16(v - __bfloat162float(h));
}

__device__ __forceinline__ void mma16(float* c, const unsigned* a, unsigned b0, unsigned b1){
    asm volatile("mma.sync.aligned.m16n8k16.row.col.f32.bf16.bf16.f32 "
        "{%0,%1,%2,%3}, {%4,%5,%6,%7}, {%8,%9}, {%0,%1,%2,%3};"
        : "+f"(c[0]),"+f"(c[1]),"+f"(c[2]),"+f"(c[3])
        : "r"(a[0]),"r"(a[1]),"r"(a[2]),"r"(a[3]), "r"(b0),"r"(b1));
}

// ---- flag reset (graph-replay safe) ----
__global__ void k_zeroflag(){ g_flag[threadIdx.x] = 0; }

// ---- K1: per-chunk totals + x split to bf16 ----
__global__ void k_chunksum(const float* __restrict__ x){
    int bc = blockIdx.x; int b = bc>>6; int c = bc&63; int t = threadIdx.x;
    int base = (b*Ss + c*CS)*HD + t;
    float acc = 0.f;
    #pragma unroll 8
    for (int s=0;s<CS;s++){
        float v = x[base + s*HD];
        acc += v;
        __nv_bfloat16 h,l; split_bf16(v,h,l);
        g_xh[base+s*HD]=h; g_xl[base+s*HD]=l;
    }
    g_ctot[bc*HD + t] = acc;
}

// ---- K2: exclusive scan of chunk totals ----
__global__ void k_chunkscan(){
    int ch = blockIdx.x*blockDim.x + threadIdx.x;
    int b = ch>>9, t = ch&511;
    float run = 0.f;
    #pragma unroll
    for (int c=0;c<NC;c++){
        int i = (b*NC + c)*HD + t;
        float v = g_ctot[i]; g_ctot[i] = run; run += v;
    }
}

// ---- K3: warp-per-chunk fused cumsum + LN + bf16 split (no barriers) ----
__global__ __launch_bounds__(32) void k_lnwarp(
    const float* __restrict__ x, const float* __restrict__ gamma,
    const float* __restrict__ beta){
    int bc = blockIdx.x; int b = bc>>6; int c = bc&63;
    int lane = threadIdx.x;
    int ch0 = lane*16;
    int base = (b*Ss + c*CS)*HD + ch0;

    float gm[16], bt[16], run[16];
    #pragma unroll
    for (int j=0;j<4;j++){
        float4 g4 = *(const float4*)(gamma + ch0 + j*4);
        float4 b4 = *(const float4*)(beta  + ch0 + j*4);
        float4 r4 = *(const float4*)(g_ctot + bc*HD + ch0 + j*4);
        gm[j*4]=g4.x; gm[j*4+1]=g4.y; gm[j*4+2]=g4.z; gm[j*4+3]=g4.w;
        bt[j*4]=b4.x; bt[j*4+1]=b4.y; bt[j*4+2]=b4.z; bt[j*4+3]=b4.w;
        run[j*4]=r4.x; run[j*4+1]=r4.y; run[j*4+2]=r4.z; run[j*4+3]=r4.w;
    }

    for (int s=0;s<CS;s++){
        float xv[16];
        #pragma unroll
        for (int j=0;j<4;j++){
            float4 v = *(const float4*)(x + base + s*HD + j*4);
            xv[j*4]=v.x; xv[j*4+1]=v.y; xv[j*4+2]=v.z; xv[j*4+3]=v.w;
        }
        float s1=0.f, s2=0.f;
        #pragma unroll
        for (int j=0;j<16;j++){ s1 += run[j]; s2 += run[j]*run[j]; }
        #pragma unroll
        for (int o=16;o;o>>=1){
            s1 += __shfl_xor_sync(0xffffffffu, s1, o);
            s2 += __shfl_xor_sync(0xffffffffu, s2, o);
        }
        float mean = s1*(1.f/512.f);
        float rinv = rsqrtf(s2*(1.f/512.f) - mean*mean + 1e-5f);
        #pragma unroll
        for (int j=0;j<4;j++){
            float w0=(run[j*4  ]-mean)*rinv*gm[j*4  ]+bt[j*4  ];
            float w1=(run[j*4+1]-mean)*rinv*gm[j*4+1]+bt[j*4+1];
            float w2=(run[j*4+2]-mean)*rinv*gm[j*4+2]+bt[j*4+2];
            float w3=(run[j*4+3]-mean)*rinv*gm[j*4+3]+bt[j*4+3];
            __nv_bfloat16 h0,l0,h1,l1,h2,l2,h3,l3;
            split_bf16(w0,h0,l0); split_bf16(w1,h1,l1);
            split_bf16(w2,h2,l2); split_bf16(w3,h3,l3);
            __nv_bfloat162 ph0=__halves2bfloat162(h0,h1), ph1=__halves2bfloat162(h2,h3);
            __nv_bfloat162 pl0=__halves2bfloat162(l0,l1), pl1=__halves2bfloat162(l2,l3);
            uint2 uh; uh.x=*(unsigned*)&ph0; uh.y=*(unsigned*)&ph1;
            uint2 ul; ul.x=*(unsigned*)&pl0; ul.y=*(unsigned*)&pl1;
            *(uint2*)(g_lnh + base + s*HD + j*4) = uh;
            *(uint2*)(g_lnl + base + s*HD + j*4) = ul;
        }
        #pragma unroll
        for (int j=0;j<16;j++) run[j] += xv[j];
    }
}

// ---- K5: GEMM1 bf16-compensated mma, M64 x N192, fused gate epilogue ----
__global__ __launch_bounds__(256,2) void k_gemm1(const float* __restrict__ bias){
    __shared__ __nv_bfloat16 Ah[2][64*24], Al[2][64*24];
    __shared__ __nv_bfloat16 Bh[2][192*24], Bl[2][192*24];
    int t = threadIdx.x;
    int r0 = blockIdx.x*64;
    int lane=t&31, wid=t>>5, wm=wid&1, wn=wid>>1;
    int g=lane>>2, tg=lane&3;

    float Cr[2][6][4];
    #pragma unroll
    for (int a=0;a<2;a++)
        #pragma unroll
        for (int b=0;b<6;b++)
            #pragma unroll
            for (int c=0;c<4;c++) Cr[a][b][c]=0.f;

    unsigned ra_h[2], ra_l[2], rb_h[6], rb_l[6];

    auto load_stage = [&](int s){
        const unsigned* gah = (const unsigned*)(s<4 ? g_xh : g_lnh);
        const unsigned* gal = (const unsigned*)(s<4 ? g_xl : g_lnl);
        int so = (s&3)*8;
        #pragma unroll
        for (int i=0;i<2;i++){
            int idx = t + i*256, row = idx>>3, c8 = idx&7;
            int gi = (r0+row)*32 + so + c8;
            ra_h[i] = gah[gi]; ra_l[i] = gal[gi];
        }
        const unsigned* gbh = (const unsigned*)g_W1h;
        const unsigned* gbl = (const unsigned*)g_W1l;
        #pragma unroll
        for (int i=0;i<6;i++){
            int idx = t + i*256, row = idx>>3, c8 = idx&7;
            int gi = row*64 + s*8 + c8;
            rb_h[i] = gbh[gi]; rb_l[i] = gbl[gi];
        }
    };
    auto store_stage = [&](int buf){
        unsigned* sah = (unsigned*)Ah[buf]; unsigned* sal = (unsigned*)Al[buf];
        #pragma unroll
        for (int i=0;i<2;i++){
            int idx = t + i*256, row = idx>>3, c8 = idx&7;
            sah[row*12+c8] = ra_h[i]; sal[row*12+c8] = ra_l[i];
        }
        unsigned* sbh = (unsigned*)Bh[buf]; unsigned* sbl = (unsigned*)Bl[buf];
        #pragma unroll
        for (int i=0;i<6;i++){
            int idx = t + i*256, row = idx>>3, c8 = idx&7;
            sbh[row*12+c8] = rb_h[i]; sbl[row*12+c8] = rb_l[i];
        }
    };

    load_stage(0); store_stage(0); __syncthreads();
    for (int s=0;s<8;s++){
        int buf = s&1;
        if (s<7) load_stage(s+1);
        const unsigned* As_h = (const unsigned*)Ah[buf];
        const unsigned* As_l = (const unsigned*)Al[buf];
        const unsigned* Bs_h = (const unsigned*)Bh[buf];
        const unsigned* Bs_l = (const unsigned*)Bl[buf];
        unsigned ah[2][4], al[2][4];
        #pragma unroll
        for (int mf=0;mf<2;mf++){
            int mr = wm*32 + mf*16;
            ah[mf][0]=As_h[(mr+g  )*12+tg  ]; ah[mf][1]=As_h[(mr+g+8)*12+tg  ];
            ah[mf][2]=As_h[(mr+g  )*12+tg+4]; ah[mf][3]=As_h[(mr+g+8)*12+tg+4];
            al[mf][0]=As_l[(mr+g  )*12+tg  ]; al[mf][1]=As_l[(mr+g+8)*12+tg  ];
            al[mf][2]=As_l[(mr+g  )*12+tg+4]; al[mf][3]=As_l[(mr+g+8)*12+tg+4];
        }
        #pragma unroll
        for (int nf=0;nf<6;nf++){
            int cb = wn*48 + nf*8 + g;
            unsigned bh0=Bs_h[cb*12+tg], bh1=Bs_h[cb*12+tg+4];
            unsigned bl0=Bs_l[cb*12+tg], bl1=Bs_l[cb*12+tg+4];
            #pragma unroll
            for (int mf=0;mf<2;mf++){
                mma16(Cr[mf][nf], ah[mf], bh0, bh1);
                mma16(Cr[mf][nf], al[mf], bh0, bh1);
                mma16(Cr[mf][nf], ah[mf], bl0, bl1);
            }
        }
        if (s<7){ store_stage((s+1)&1); __syncthreads(); }
    }
    #pragma unroll
    for (int mf=0;mf<2;mf++)
        #pragma unroll
        for (int nfd=0;nfd<2;nfd++)
            #pragma unroll
            for (int j=0;j<4;j++){
                int row = r0 + wm*32 + mf*16 + g + ((j>>1)<<3);
                int d = wn*16 + nfd*8 + 2*tg + (j&1);
                float ig  = Cr[mf][nfd  ][j] + __ldg(&bias[d]);
                float fgv = Cr[mf][nfd+2][j] + __ldg(&bias[64+d]);
                float hd  = Cr[mf][nfd+4][j] + __ldg(&bias[128+d]);
                g_fg [row*64+d] = sigmf(fgv);
                g_igh[row*64+d] = sigmf(ig)*fmaxf(hd,0.f);
            }
}

// ---- K6: single-pass decoupled-lookback scan -> cell (bf16 hi/lo) ----
__global__ __launch_bounds__(512) void k_scan(const float* __restrict__ initcx){
    int bc = blockIdx.x; int b = bc>>6; int c = bc&63; int t = threadIdx.x;
    int base = (b*Ss + c*CS)*HD + t;

    // phase 1: chunk aggregate (a, b)
    float a = 1.f, bv = 0.f;
    #pragma unroll 8
    for (int s=0;s<CS;s++){
        float f = g_fg[base + s*HD];
        float g = g_igh[base + s*HD];
        a *= f; bv = bv*f + g;
    }
    g_a[bc*HD + t] = a; g_bv[bc*HD + t] = bv;
    __threadfence();
    __syncthreads();
    if (t==0) atomicExch(&g_flag[bc], 1);

    // phase 2: wait for predecessors, compose carry
    float cell = initcx[t];
    if (c > 0){
        if (t < c){
            volatile int* fl = &g_flag[b*64 + t];
            while (*fl == 0) { }
        }
        __syncthreads();
        __threadfence();
        for (int p=0;p<c;p++){
            int idx = (b*64 + p)*HD + t;
            cell = g_a[idx]*cell + g_bv[idx];
        }
    }

    // phase 3: replay recurrence, emit bf16 hi/lo cell
    #pragma unroll 4
    for (int s=0;s<CS;s++){
        float f = g_fg[base + s*HD];
        float g = g_igh[base + s*HD];
        cell = f*cell + g;
        __nv_bfloat16 h,l; split_bf16(cell,h,l);
        g_ch[base+s*HD]=h; g_cl[base+s*HD]=l;
    }
}

// ---- P0: weight transpose + remap + split ----
__global__ void k_prepw(const float* __restrict__ W1, const float* __restrict__ W2){
    int c = blockIdx.x, k = threadIdx.x;
    if (c < 192){
        int wn=c/48, rem=c%48, gate=rem>>4, dd=rem&15;
        float v = W1[k*192 + gate*64 + wn*16 + dd];
        __nv_bfloat16 h,l; split_bf16(v,h,l);
        g_W1h[c*128+k]=h; g_W1l[c*128+k]=l;
    } else {
        int c2 = c-192;
        float v = W2[k*64 + c2];
        __nv_bfloat16 h,l; split_bf16(v,h,l);
        g_W2h[c2*128+k]=h; g_W2l[c2*128+k]=l;
    }
}

// ---- K9: GEMM2 bf16-compensated mma, fused og*cell (cell = hi+lo) ----
__global__ __launch_bounds__(256,2) void k_gemm2(const float* __restrict__ bias,
                                                 float* __restrict__ out){
    __shared__ __nv_bfloat16 Ah[2][64*24], Al[2][64*24];
    __shared__ __nv_bfloat16 Bh[2][64*24], Bl[2][64*24];
    int t = threadIdx.x;
    int r0 = blockIdx.x*64;
    int lane=t&31, wid=t>>5, wm=wid&1, wn=wid>>1;
    int g=lane>>2, tg=lane&3;

    float Cr[2][2][4];
    #pragma unroll
    for (int a=0;a<2;a++)
        #pragma unroll
        for (int b=0;b<2;b++)
            #pragma unroll
            for (int c=0;c<4;c++) Cr[a][b][c]=0.f;

    unsigned ra_h[2], ra_l[2], rb_h[2], rb_l[2];
    auto load_stage = [&](int s){
        const unsigned* gah = (const unsigned*)(s<4 ? g_xh : g_ch);
        const unsigned* gal = (const unsigned*)(s<4 ? g_xl : g_cl);
        int so = (s&3)*8;
        #pragma unroll
        for (int i=0;i<2;i++){
            int idx = t + i*256, row = idx>>3, c8 = idx&7;
            int gi = (r0+row)*32 + so + c8;
            ra_h[i] = gah[gi]; ra_l[i] = gal[gi];
        }
        const unsigned* gbh = (const unsigned*)g_W2h;
        const unsigned* gbl = (const unsigned*)g_W2l;
        #pragma unroll
        for (int i=0;i<2;i++){
            int idx = t + i*256, row = idx>>3, c8 = idx&7;
            int gi = row*64 + s*8 + c8;
            rb_h[i] = gbh[gi]; rb_l[i] = gbl[gi];
        }
    };
    auto store_stage = [&](int buf){
        unsigned* sah=(unsigned*)Ah[buf]; unsigned* sal=(unsigned*)Al[buf];
        unsigned* sbh=(unsigned*)Bh[buf]; unsigned* sbl=(unsigned*)Bl[buf];
        #pragma unroll
        for (int i=0;i<2;i++){
            int idx = t + i*256, row = idx>>3, c8 = idx&7;
            sah[row*12+c8]=ra_h[i]; sal[row*12+c8]=ra_l[i];
            sbh[row*12+c8]=rb_h[i]; sbl[row*12+c8]=rb_l[i];
        }
    };

    load_stage(0); store_stage(0); __syncthreads();
    for (int s=0;s<8;s++){
        int buf = s&1;
        if (s<7) load_stage(s+1);
        const unsigned* As_h=(const unsigned*)Ah[buf];
        const unsigned* As_l=(const unsigned*)Al[buf];
        const unsigned* Bs_h=(const unsigned*)Bh[buf];
        const unsigned* Bs_l=(const unsigned*)Bl[buf];
        unsigned ah[2][4], al[2][4];
        #pragma unroll
        for (int mf=0;mf<2;mf++){
            int mr = wm*32 + mf*16;
            ah[mf][0]=As_h[(mr+g  )*12+tg  ]; ah[mf][1]=As_h[(mr+g+8)*12+tg  ];
            ah[mf][2]=As_h[(mr+g  )*12+tg+4]; ah[mf][3]=As_h[(mr+g+8)*12+tg+4];
            al[mf][0]=As_l[(mr+g  )*12+tg  ]; al[mf][1]=As_l[(mr+g+8)*12+tg  ];
            al[mf][2]=As_l[(mr+g  )*12+tg+4]; al[mf][3]=As_l[(mr+g+8)*12+tg+4];
        }
        #pragma unroll
        for (int nf=0;nf<2;nf++){
            int cb = wn*16 + nf*8 + g;
            unsigned bh0=Bs_h[cb*12+tg], bh1=Bs_h[cb*12+tg+4];
            unsigned bl0=Bs_l[cb*12+tg], bl1=Bs_l[cb*12+tg+4];
            #pragma unroll
            for (int mf=0;mf<2;mf++){
                mma16(Cr[mf][nf], ah[mf], bh0, bh1);
                mma16(Cr[mf][nf], al[mf], bh0, bh1);
                mma16(Cr[mf][nf], ah[mf], bl0, bl1);
            }
        }
        if (s<7){ store_stage((s+1)&1); __syncthreads(); }
    }
    #pragma unroll
    for (int mf=0;mf<2;mf++)
        #pragma unroll
        for (int nf=0;nf<2;nf++)
            #pragma unroll
            for (int j=0;j<4;j++){
                int row = r0 + wm*32 + mf*16 + g + ((j>>1)<<3);
                int col = wn*16 + nf*8 + 2*tg + (j&1);
                float og = sigmf(Cr[mf][nf][j] + __ldg(&bias[col]));
                float cell = __bfloat162float(g_ch[row*64+col]) +
                             __bfloat162float(g_cl[row*64+col]);
                out[row*64+col] = og * cell;
            }
}

extern "C" void kernel_launch(void* const* d_in, const int* in_sizes, int n_in,
                              void* d_out, int out_size){
    const float* x      = (const float*)d_in[0];
    const float* W_hid  = (const float*)d_in[1];
    const float* b_hid  = (const float*)d_in[2];
    const float* W_og   = (const float*)d_in[3];
    const float* b_og   = (const float*)d_in[4];
    const float* gamma  = (const float*)d_in[5];
    const float* beta   = (const float*)d_in[6];
    const float* initcx = (const float*)d_in[7];
    float* out = (float*)d_out;

    k_zeroflag <<<1, Bb*NC>>>();
    k_chunksum <<<Bb*NC, 512>>>(x);
    k_chunkscan<<<16, 128>>>();
    k_lnwarp   <<<Bb*NC, 32>>>(x, gamma, beta);   // profiled slot (4th launch)
    k_prepw    <<<256, 128>>>(W_hid, W_og);
    k_gemm1    <<<Mm/64, 256>>>(b_hid);
    k_scan     <<<Bb*NC, 512>>>(initcx);
    k_gemm2    <<<Mm/64, 256>>>(b_og, out);
}

// round 7
// speedup vs baseline: 1.0966x; 1.0966x over previous
#include <cuda_runtime.h>
#include <cuda_bf16.h>
#include <math.h>

#define Bb 4
#define Ss 4096
#define Hh 8
#define Dd 64
#define HD 512
#define NC 64
#define CS 64
#define BSn 16384
#define Mm 131072          // B*S*H rows
#define MD (Mm*64)         // 8.39M elems

// ---- fp32 scratch ----
__device__ float g_csum[MD];
__device__ float g_fg  [MD];
__device__ float g_igh [MD];
__device__ float g_ctot[Bb*NC*HD];
__device__ float g_a   [Bb*NC*HD];
__device__ float g_bv  [Bb*NC*HD];
__device__ int   g_flag[Bb*NC];
// ---- bf16 hi/lo operand scratch ----
__device__ __nv_bfloat16 g_xh[MD], g_xl[MD];
__device__ __nv_bfloat16 g_lnh[MD], g_lnl[MD];
__device__ __nv_bfloat16 g_ch[MD], g_cl[MD];
__device__ __nv_bfloat16 g_W1h[192*128], g_W1l[192*128];   // [c][k], gate-remapped
__device__ __nv_bfloat16 g_W2h[64*128],  g_W2l[64*128];    // [n][k]

__device__ __forceinline__ float sigmf(float z){ return 1.f/(1.f+__expf(-z)); }

__device__ __forceinline__ void split_bf16(float v, __nv_bfloat16 &h, __nv_bfloat16 &l){
    h = __float2bfloat16(v);
    l = __float2bfloat16(v - __bfloat162float(h));
}

__device__ __forceinline__ void mma16(float* c, const unsigned* a, unsigned b0, unsigned b1){
    asm volatile("mma.sync.aligned.m16n8k16.row.col.f32.bf16.bf16.f32 "
        "{%0,%1,%2,%3}, {%4,%5,%6,%7}, {%8,%9}, {%0,%1,%2,%3};"
        : "+f"(c[0]),"+f"(c[1]),"+f"(c[2]),"+f"(c[3])
        : "r"(a[0]),"r"(a[1]),"r"(a[2]),"r"(a[3]), "r"(b0),"r"(b1));
}

// ---- P0: weight transpose + remap + split ----
__global__ void k_prepw(const float* __restrict__ W1, const float* __restrict__ W2){
    int c = blockIdx.x, k = threadIdx.x;
    if (c < 192){
        int wn=c/48, rem=c%48, gate=rem>>4, dd=rem&15;
        float v = W1[k*192 + gate*64 + wn*16 + dd];
        __nv_bfloat16 h,l; split_bf16(v,h,l);
        g_W1h[c*128+k]=h; g_W1l[c*128+k]=l;
    } else {
        int c2 = c-192;
        float v = W2[k*64 + c2];
        __nv_bfloat16 h,l; split_bf16(v,h,l);
        g_W2h[c2*128+k]=h; g_W2l[c2*128+k]=l;
    }
}

// ---- K1: per-chunk totals + x split to bf16 ----
__global__ void k_chunksum(const float* __restrict__ x){
    int bc = blockIdx.x; int b = bc>>6; int c = bc&63; int t = threadIdx.x;
    int base = (b*Ss + c*CS)*HD + t;
    float acc = 0.f;
    #pragma unroll 8
    for (int s=0;s<CS;s++){
        float v = x[base + s*HD];
        acc += v;
        __nv_bfloat16 h,l; split_bf16(v,h,l);
        g_xh[base+s*HD]=h; g_xl[base+s*HD]=l;
    }
    g_ctot[bc*HD + t] = acc;
}

// ---- K2: exclusive scan of chunk totals (+ zero the lookback flags) ----
__global__ void k_chunkscan(){
    int ch = blockIdx.x*blockDim.x + threadIdx.x;
    if (ch < Bb*NC) g_flag[ch] = 0;
    int b = ch>>9, t = ch&511;
    float run = 0.f;
    #pragma unroll
    for (int c=0;c<NC;c++){
        int i = (b*NC + c)*HD + t;
        float v = g_ctot[i]; g_ctot[i] = run; run += v;
    }
}

// ---- K3: materialize exclusive cumsum ----
__global__ void k_csum(const float* __restrict__ x){
    int bc = blockIdx.x; int b = bc>>6; int c = bc&63; int t = threadIdx.x;
    float run = g_ctot[bc*HD + t];
    int base = (b*Ss + c*CS)*HD + t;
    #pragma unroll 8
    for (int s=0;s<CS;s++){
        g_csum[base + s*HD] = run;
        run += x[base + s*HD];
    }
}

// ---- K4: LN stats + normalize + split (one warp per (b,s) row) ----
__global__ __launch_bounds__(512) void k_ln(const float* __restrict__ gamma,
                                            const float* __restrict__ beta){
    __shared__ float gsm[512], bsm[512];
    int t = threadIdx.x;
    gsm[t]=gamma[t]; bsm[t]=beta[t];
    __syncthreads();
    int lane = t&31;
    int row = blockIdx.x*16 + (t>>5);
    const float4* src = (const float4*)(g_csum + row*512);
    float4 v[4]; float s1=0.f, s2=0.f;
    #pragma unroll
    for (int i=0;i<4;i++){
        v[i] = src[i*32+lane];
        s1 += v[i].x+v[i].y+v[i].z+v[i].w;
        s2 += v[i].x*v[i].x+v[i].y*v[i].y+v[i].z*v[i].z+v[i].w*v[i].w;
    }
    #pragma unroll
    for (int o=16;o;o>>=1){
        s1 += __shfl_xor_sync(0xffffffffu, s1, o);
        s2 += __shfl_xor_sync(0xffffffffu, s2, o);
    }
    float mean = s1*(1.f/512.f);
    float rinv = rsqrtf(s2*(1.f/512.f) - mean*mean + 1e-5f);
    #pragma unroll
    for (int i=0;i<4;i++){
        int e0 = (i*32+lane)*4;
        float w0 = (v[i].x-mean)*rinv*gsm[e0  ]+bsm[e0  ];
        float w1 = (v[i].y-mean)*rinv*gsm[e0+1]+bsm[e0+1];
        float w2 = (v[i].z-mean)*rinv*gsm[e0+2]+bsm[e0+2];
        float w3 = (v[i].w-mean)*rinv*gsm[e0+3]+bsm[e0+3];
        __nv_bfloat16 h0,l0,h1,l1,h2,l2,h3,l3;
        split_bf16(w0,h0,l0); split_bf16(w1,h1,l1);
        split_bf16(w2,h2,l2); split_bf16(w3,h3,l3);
        __nv_bfloat162 ph0 = __halves2bfloat162(h0,h1), ph1 = __halves2bfloat162(h2,h3);
        __nv_bfloat162 pl0 = __halves2bfloat162(l0,l1), pl1 = __halves2bfloat162(l2,l3);
        uint2 uh; uh.x = *(unsigned*)&ph0; uh.y = *(unsigned*)&ph1;
        uint2 ul; ul.x = *(unsigned*)&pl0; ul.y = *(unsigned*)&pl1;
        ((uint2*)(g_lnh + row*512))[i*32+lane] = uh;
        ((uint2*)(g_lnl + row*512))[i*32+lane] = ul;
    }
}

// ---- K5: GEMM1 bf16-compensated mma, M64 x N96 (half d-space), 4 CTA/SM ----
__global__ __launch_bounds__(256,4) void k_gemm1(const float* __restrict__ bias){
    __shared__ __nv_bfloat16 Ah[2][64*24], Al[2][64*24];
    __shared__ __nv_bfloat16 Bh[2][96*24], Bl[2][96*24];
    int t = threadIdx.x;
    int r0 = blockIdx.x*64;
    int y  = blockIdx.y;                 // d-half: wn_g in {2y, 2y+1}
    int lane=t&31, wid=t>>5, wm=wid&3, wn=wid>>2;
    int g=lane>>2, tg=lane&3;

    float Cr[6][4];
    #pragma unroll
    for (int b=0;b<6;b++)
        #pragma unroll
        for (int c=0;c<4;c++) Cr[b][c]=0.f;

    unsigned ra_h[2], ra_l[2], rb_h[3], rb_l[3];

    auto load_stage = [&](int s){
        const unsigned* gah = (const unsigned*)(s<4 ? g_xh : g_lnh);
        const unsigned* gal = (const unsigned*)(s<4 ? g_xl : g_lnl);
        int so = (s&3)*8;
        #pragma unroll
        for (int i=0;i<2;i++){
            int idx = t + i*256, row = idx>>3, c8 = idx&7;
            int gi = (r0+row)*32 + so + c8;
            ra_h[i] = gah[gi]; ra_l[i] = gal[gi];
        }
        const unsigned* gbh = (const unsigned*)g_W1h;
        const unsigned* gbl = (const unsigned*)g_W1l;
        #pragma unroll
        for (int i=0;i<3;i++){
            int idx = t + i*256, row = idx>>3, c8 = idx&7;
            int gi = (96*y + row)*64 + s*8 + c8;
            rb_h[i] = gbh[gi]; rb_l[i] = gbl[gi];
        }
    };
    auto store_stage = [&](int buf){
        unsigned* sah = (unsigned*)Ah[buf]; unsigned* sal = (unsigned*)Al[buf];
        #pragma unroll
        for (int i=0;i<2;i++){
            int idx = t + i*256, row = idx>>3, c8 = idx&7;
            sah[row*12+c8] = ra_h[i]; sal[row*12+c8] = ra_l[i];
        }
        unsigned* sbh = (unsigned*)Bh[buf]; unsigned* sbl = (unsigned*)Bl[buf];
        #pragma unroll
        for (int i=0;i<3;i++){
            int idx = t + i*256, row = idx>>3, c8 = idx&7;
            sbh[row*12+c8] = rb_h[i]; sbl[row*12+c8] = rb_l[i];
        }
    };

    load_stage(0); store_stage(0); __syncthreads();
    for (int s=0;s<8;s++){
        int buf = s&1;
        if (s<7) load_stage(s+1);
        const unsigned* As_h = (const unsigned*)Ah[buf];
        const unsigned* As_l = (const unsigned*)Al[buf];
        const unsigned* Bs_h = (const unsigned*)Bh[buf];
        const unsigned* Bs_l = (const unsigned*)Bl[buf];
        #pragma unroll
        for (int ks=0;ks<2;ks++){
            int ko = ks*4;
            unsigned ah[4], al[4];
            int mr = wm*16;
            ah[0]=As_h[(mr+g  )*12+ko+tg]; ah[1]=As_h[(mr+g+8)*12+ko+tg];
            ah[2]=As_h[(mr+g  )*12+ko+tg+4]; ah[3]=As_h[(mr+g+8)*12+ko+tg+4];
            al[0]=As_l[(mr+g  )*12+ko+tg]; al[1]=As_l[(mr+g+8)*12+ko+tg];
            al[2]=As_l[(mr+g  )*12+ko+tg+4]; al[3]=As_l[(mr+g+8)*12+ko+tg+4];
            // note: ks indexes two k=8 halves? m16n8k16 consumes full 16 -> single ks
            (void)ko;
            #pragma unroll
            for (int nf=0;nf<6;nf++){
                int cb = wn*48 + nf*8 + g;
                unsigned bh0=Bs_h[cb*12+ko+tg], bh1=Bs_h[cb*12+ko+tg+4];
                unsigned bl0=Bs_l[cb*12+ko+tg], bl1=Bs_l[cb*12+ko+tg+4];
                mma16(Cr[nf], ah, bh0, bh1);
                mma16(Cr[nf], al, bh0, bh1);
                mma16(Cr[nf], ah, bl0, bl1);
            }
            break;  // k16 stage consumed in one shot (12 words/row = 24 bf16 >= 16)
        }
        if (s<7){ store_stage((s+1)&1); __syncthreads(); }
    }
    #pragma unroll
    for (int nfd=0;nfd<2;nfd++)
        #pragma unroll
        for (int j=0;j<4;j++){
            int row = r0 + wm*16 + g + ((j>>1)<<3);
            int colf = 2*tg + (j&1);
            int dd = nfd*8 + colf;
            int d = (2*y + wn)*16 + dd;
            float ig  = Cr[nfd  ][j] + __ldg(&bias[d]);
            float fgv = Cr[nfd+2][j] + __ldg(&bias[64+d]);
            float hd  = Cr[nfd+4][j] + __ldg(&bias[128+d]);
            g_fg [row*64+d] = sigmf(fgv);
            g_igh[row*64+d] = sigmf(ig)*fmaxf(hd,0.f);
        }
}

// ---- K6: single-pass decoupled-lookback scan -> cell (bf16 hi/lo) ----
__global__ __launch_bounds__(512) void k_scan(const float* __restrict__ initcx){
    int bc = blockIdx.x; int b = bc>>6; int c = bc&63; int t = threadIdx.x;
    int base = (b*Ss + c*CS)*HD + t;

    float a = 1.f, bv = 0.f;
    #pragma unroll 8
    for (int s=0;s<CS;s++){
        float f = g_fg[base + s*HD];
        float g = g_igh[base + s*HD];
        a *= f; bv = bv*f + g;
    }
    g_a[bc*HD + t] = a; g_bv[bc*HD + t] = bv;
    __threadfence();
    __syncthreads();
    if (t==0) atomicExch(&g_flag[bc], 1);

    float cell = initcx[t];
    if (c > 0){
        if (t < c){
            volatile int* fl = &g_flag[b*64 + t];
            while (*fl == 0) { }
        }
        __syncthreads();
        __threadfence();
        for (int p=0;p<c;p++){
            int idx = (b*64 + p)*HD + t;
            cell = g_a[idx]*cell + g_bv[idx];
        }
    }

    #pragma unroll 4
    for (int s=0;s<CS;s++){
        float f = g_fg[base + s*HD];
        float g = g_igh[base + s*HD];
        cell = f*cell + g;
        __nv_bfloat16 h,l; split_bf16(cell,h,l);
        g_ch[base+s*HD]=h; g_cl[base+s*HD]=l;
    }
}

// ---- K9: GEMM2 bf16-compensated mma, fused og*cell ----
__global__ __launch_bounds__(256,4) void k_gemm2(const float* __restrict__ bias,
                                                 float* __restrict__ out){
    __shared__ __nv_bfloat16 Ah[2][64*24], Al[2][64*24];
    __shared__ __nv_bfloat16 Bh[2][64*24], Bl[2][64*24];
    int t = threadIdx.x;
    int r0 = blockIdx.x*64;
    int lane=t&31, wid=t>>5, wm=wid&1, wn=wid>>1;
    int g=lane>>2, tg=lane&3;

    float Cr[2][2][4];
    #pragma unroll
    for (int a=0;a<2;a++)
        #pragma unroll
        for (int b=0;b<2;b++)
            #pragma unroll
            for (int c=0;c<4;c++) Cr[a][b][c]=0.f;

    unsigned ra_h[2], ra_l[2], rb_h[2], rb_l[2];
    auto load_stage = [&](int s){
        const unsigned* gah = (const unsigned*)(s<4 ? g_xh : g_ch);
        const unsigned* gal = (const unsigned*)(s<4 ? g_xl : g_cl);
        int so = (s&3)*8;
        #pragma unroll
        for (int i=0;i<2;i++){
            int idx = t + i*256, row = idx>>3, c8 = idx&7;
            int gi = (r0+row)*32 + so + c8;
            ra_h[i] = gah[gi]; ra_l[i] = gal[gi];
        }
        const unsigned* gbh = (const unsigned*)g_W2h;
        const unsigned* gbl = (const unsigned*)g_W2l;
        #pragma unroll
        for (int i=0;i<2;i++){
            int idx = t + i*256, row = idx>>3, c8 = idx&7;
            int gi = row*64 + s*8 + c8;
            rb_h[i] = gbh[gi]; rb_l[i] = gbl[gi];
        }
    };
    auto store_stage = [&](int buf){
        unsigned* sah=(unsigned*)Ah[buf]; unsigned* sal=(unsigned*)Al[buf];
        unsigned* sbh=(unsigned*)Bh[buf]; unsigned* sbl=(unsigned*)Bl[buf];
        #pragma unroll
        for (int i=0;i<2;i++){
            int idx = t + i*256, row = idx>>3, c8 = idx&7;
            sah[row*12+c8]=ra_h[i]; sal[row*12+c8]=ra_l[i];
            sbh[row*12+c8]=rb_h[i]; sbl[row*12+c8]=rb_l[i];
        }
    };

    load_stage(0); store_stage(0); __syncthreads();
    for (int s=0;s<8;s++){
        int buf = s&1;
        if (s<7) load_stage(s+1);
        const unsigned* As_h=(const unsigned*)Ah[buf];
        const unsigned* As_l=(const unsigned*)Al[buf];
        const unsigned* Bs_h=(const unsigned*)Bh[buf];
        const unsigned* Bs_l=(const unsigned*)Bl[buf];
        unsigned ah[2][4], al[2][4];
        #pragma unroll
        for (int mf=0;mf<2;mf++){
            int mr = wm*32 + mf*16;
            ah[mf][0]=As_h[(mr+g  )*12+tg  ]; ah[mf][1]=As_h[(mr+g+8)*12+tg  ];
            ah[mf][2]=As_h[(mr+g  )*12+tg+4]; ah[mf][3]=As_h[(mr+g+8)*12+tg+4];
            al[mf][0]=As_l[(mr+g  )*12+tg  ]; al[mf][1]=As_l[(mr+g+8)*12+tg  ];
            al[mf][2]=As_l[(mr+g  )*12+tg+4]; al[mf][3]=As_l[(mr+g+8)*12+tg+4];
        }
        #pragma unroll
        for (int nf=0;nf<2;nf++){
            int cb = wn*16 + nf*8 + g;
            unsigned bh0=Bs_h[cb*12+tg], bh1=Bs_h[cb*12+tg+4];
            unsigned bl0=Bs_l[cb*12+tg], bl1=Bs_l[cb*12+tg+4];
            #pragma unroll
            for (int mf=0;mf<2;mf++){
                mma16(Cr[mf][nf], ah[mf], bh0, bh1);
                mma16(Cr[mf][nf], al[mf], bh0, bh1);
                mma16(Cr[mf][nf], ah[mf], bl0, bl1);
            }
        }
        if (s<7){ store_stage((s+1)&1); __syncthreads(); }
    }
    #pragma unroll
    for (int mf=0;mf<2;mf++)
        #pragma unroll
        for (int nf=0;nf<2;nf++)
            #pragma unroll
            for (int j=0;j<4;j++){
                int row = r0 + wm*32 + mf*16 + g + ((j>>1)<<3);
                int col = wn*16 + nf*8 + 2*tg + (j&1);
                float og = sigmf(Cr[mf][nf][j] + __ldg(&bias[col]));
                float cell = __bfloat162float(g_ch[row*64+col]) +
                             __bfloat162float(g_cl[row*64+col]);
                out[row*64+col] = og * cell;
            }
}

extern "C" void kernel_launch(void* const* d_in, const int* in_sizes, int n_in,
                              void* d_out, int out_size){
    const float* x      = (const float*)d_in[0];
    const float* W_hid  = (const float*)d_in[1];
    const float* b_hid  = (const float*)d_in[2];
    const float* W_og   = (const float*)d_in[3];
    const float* b_og   = (const float*)d_in[4];
    const float* gamma  = (const float*)d_in[5];
    const float* beta   = (const float*)d_in[6];
    const float* initcx = (const float*)d_in[7];
    float* out = (float*)d_out;

    k_prepw    <<<256, 128>>>(W_hid, W_og);
    k_chunksum <<<Bb*NC, 512>>>(x);
    k_chunkscan<<<16, 128>>>();
    k_csum     <<<Bb*NC, 512>>>(x);
    k_ln       <<<BSn/16, 512>>>(gamma, beta);
    k_gemm1    <<<dim3(Mm/64, 2), 256>>>(b_hid);
    k_scan     <<<Bb*NC, 512>>>(initcx);
    k_gemm2    <<<Mm/64, 256>>>(b_og, out);
}

// round 9
// speedup vs baseline: 1.5024x; 1.3701x over previous
#include <cuda_runtime.h>
#include <cuda_fp16.h>
#include <math.h>

#define Bb 4
#define Ss 4096
#define Hh 8
#define Dd 64
#define HD 512
#define NC 64
#define CS 64
#define BSn 16384
#define Mm 131072          // B*S*H rows
#define MD (Mm*64)         // 8.39M elems

// ---- fp32 scratch ----
__device__ float g_csum[MD];
__device__ float g_fg  [MD];
__device__ float g_igh [MD];
__device__ float g_cell[MD];
__device__ float g_ctot[Bb*NC*HD];
__device__ float g_a   [Bb*NC*HD];
__device__ float g_bv  [Bb*NC*HD];
__device__ int   g_flag[Bb*NC];
// ---- fp16 operand scratch ----
__device__ __half g_xh[MD];
__device__ __half g_lnh[MD];
__device__ __half g_ch[MD];
__device__ __half g_W1h[192*128];   // [c][k], gate-remapped
__device__ __half g_W2h[64*128];    // [n][k]

__device__ __forceinline__ float sigmf(float z){ return 1.f/(1.f+__expf(-z)); }

__device__ __forceinline__ void mma16(float* c, const unsigned* a, unsigned b0, unsigned b1){
    asm volatile("mma.sync.aligned.m16n8k16.row.col.f32.f16.f16.f32 "
        "{%0,%1,%2,%3}, {%4,%5,%6,%7}, {%8,%9}, {%0,%1,%2,%3};"
        : "+f"(c[0]),"+f"(c[1]),"+f"(c[2]),"+f"(c[3])
        : "r"(a[0]),"r"(a[1]),"r"(a[2]),"r"(a[3]), "r"(b0),"r"(b1));
}

// ---- P0: weight transpose + gate remap -> fp16 ----
__global__ void k_prepw(const float* __restrict__ W1, const float* __restrict__ W2){
    int c = blockIdx.x, k = threadIdx.x;
    if (c < 192){
        int wn=c/48, rem=c%48, gate=rem>>4, dd=rem&15;
        g_W1h[c*128+k] = __float2half(W1[k*192 + gate*64 + wn*16 + dd]);
    } else {
        int c2 = c-192;
        g_W2h[c2*128+k] = __float2half(W2[k*64 + c2]);
    }
}

// ---- K1: per-chunk totals + x -> fp16 ----
__global__ void k_chunksum(const float* __restrict__ x){
    int bc = blockIdx.x; int b = bc>>6; int c = bc&63; int t = threadIdx.x;
    int base = (b*Ss + c*CS)*HD + t;
    float acc = 0.f;
    #pragma unroll 8
    for (int s=0;s<CS;s++){
        float v = x[base + s*HD];
        acc += v;
        g_xh[base+s*HD] = __float2half(v);
    }
    g_ctot[bc*HD + t] = acc;
}

// ---- K2: exclusive scan of chunk totals (+ zero lookback flags) ----
__global__ void k_chunkscan(){
    int ch = blockIdx.x*blockDim.x + threadIdx.x;
    if (ch < Bb*NC) g_flag[ch] = 0;
    int b = ch>>9, t = ch&511;
    float run = 0.f;
    #pragma unroll
    for (int c=0;c<NC;c++){
        int i = (b*NC + c)*HD + t;
        float v = g_ctot[i]; g_ctot[i] = run; run += v;
    }
}

// ---- K3: materialize exclusive cumsum ----
__global__ void k_csum(const float* __restrict__ x){
    int bc = blockIdx.x; int b = bc>>6; int c = bc&63; int t = threadIdx.x;
    float run = g_ctot[bc*HD + t];
    int base = (b*Ss + c*CS)*HD + t;
    #pragma unroll 8
    for (int s=0;s<CS;s++){
        g_csum[base + s*HD] = run;
        run += x[base + s*HD];
    }
}

// ---- K4: LN stats + normalize -> fp16 (one warp per (b,s) row) ----
__global__ __launch_bounds__(512) void k_ln(const float* __restrict__ gamma,
                                            const float* __restrict__ beta){
    __shared__ float gsm[512], bsm[512];
    int t = threadIdx.x;
    gsm[t]=gamma[t]; bsm[t]=beta[t];
    __syncthreads();
    int lane = t&31;
    int row = blockIdx.x*16 + (t>>5);
    const float4* src = (const float4*)(g_csum + row*512);
    float4 v[4]; float s1=0.f, s2=0.f;
    #pragma unroll
    for (int i=0;i<4;i++){
        v[i] = src[i*32+lane];
        s1 += v[i].x+v[i].y+v[i].z+v[i].w;
        s2 += v[i].x*v[i].x+v[i].y*v[i].y+v[i].z*v[i].z+v[i].w*v[i].w;
    }
    #pragma unroll
    for (int o=16;o;o>>=1){
        s1 += __shfl_xor_sync(0xffffffffu, s1, o);
        s2 += __shfl_xor_sync(0xffffffffu, s2, o);
    }
    float mean = s1*(1.f/512.f);
    float rinv = rsqrtf(s2*(1.f/512.f) - mean*mean + 1e-5f);
    #pragma unroll
    for (int i=0;i<4;i++){
        int e0 = (i*32+lane)*4;
        float w0 = (v[i].x-mean)*rinv*gsm[e0  ]+bsm[e0  ];
        float w1 = (v[i].y-mean)*rinv*gsm[e0+1]+bsm[e0+1];
        float w2 = (v[i].z-mean)*rinv*gsm[e0+2]+bsm[e0+2];
        float w3 = (v[i].w-mean)*rinv*gsm[e0+3]+bsm[e0+3];
        __half2 p0 = __floats2half2_rn(w0,w1);
        __half2 p1 = __floats2half2_rn(w2,w3);
        uint2 u; u.x = *(unsigned*)&p0; u.y = *(unsigned*)&p1;
        ((uint2*)(g_lnh + row*512))[i*32+lane] = u;
    }
}

// ---- K5: GEMM1 fp16 mma, CTA tile M64 x N96 (d-half via blockIdx.y) ----
__global__ __launch_bounds__(256,4) void k_gemm1(const float* __restrict__ bias){
    __shared__ __half Ah[2][64*24];
    __shared__ __half Bh[2][96*24];
    int t = threadIdx.x;
    int r0 = blockIdx.x*64;
    int y  = blockIdx.y;
    int lane=t&31, wid=t>>5, wm=wid&3, wn=wid>>2;
    int g=lane>>2, tg=lane&3;

    float Cr[6][4];
    #pragma unroll
    for (int b=0;b<6;b++)
        #pragma unroll
        for (int c=0;c<4;c++) Cr[b][c]=0.f;

    unsigned ra[2], rb[3];
    auto load_stage = [&](int s){
        const unsigned* ga = (const unsigned*)(s<4 ? g_xh : g_lnh);
        int so = (s&3)*8;
        #pragma unroll
        for (int i=0;i<2;i++){
            int idx = t + i*256, row = idx>>3, c8 = idx&7;
            ra[i] = ga[(r0+row)*32 + so + c8];
        }
        const unsigned* gb = (const unsigned*)g_W1h;
        #pragma unroll
        for (int i=0;i<3;i++){
            int idx = t + i*256, row = idx>>3, c8 = idx&7;
            rb[i] = gb[(96*y + row)*64 + s*8 + c8];
        }
    };
    auto store_stage = [&](int buf){
        unsigned* sa = (unsigned*)Ah[buf];
        #pragma unroll
        for (int i=0;i<2;i++){
            int idx = t + i*256, row = idx>>3, c8 = idx&7;
            sa[row*12+c8] = ra[i];
        }
        unsigned* sbm = (unsigned*)Bh[buf];
        #pragma unroll
        for (int i=0;i<3;i++){
            int idx = t + i*256, row = idx>>3, c8 = idx&7;
            sbm[row*12+c8] = rb[i];
        }
    };

    load_stage(0); store_stage(0); __syncthreads();
    for (int s=0;s<8;s++){
        int buf = s&1;
        if (s<7) load_stage(s+1);
        const unsigned* As = (const unsigned*)Ah[buf];
        const unsigned* Bs = (const unsigned*)Bh[buf];
        unsigned a[4];
        int mr = wm*16;
        a[0]=As[(mr+g  )*12+tg  ]; a[1]=As[(mr+g+8)*12+tg  ];
        a[2]=As[(mr+g  )*12+tg+4]; a[3]=As[(mr+g+8)*12+tg+4];
        #pragma unroll
        for (int nf=0;nf<6;nf++){
            int cb = wn*48 + nf*8 + g;
            unsigned b0=Bs[cb*12+tg], b1=Bs[cb*12+tg+4];
            mma16(Cr[nf], a, b0, b1);
        }
        if (s<7){ store_stage((s+1)&1); __syncthreads(); }
    }
    #pragma unroll
    for (int nfd=0;nfd<2;nfd++)
        #pragma unroll
        for (int j=0;j<4;j++){
            int row = r0 + wm*16 + g + ((j>>1)<<3);
            int colf = 2*tg + (j&1);
            int d = (2*y + wn)*16 + nfd*8 + colf;
            float ig  = Cr[nfd  ][j] + __ldg(&bias[d]);
            float fgv = Cr[nfd+2][j] + __ldg(&bias[64+d]);
            float hd  = Cr[nfd+4][j] + __ldg(&bias[128+d]);
            g_fg [row*64+d] = sigmf(fgv);
            g_igh[row*64+d] = sigmf(ig)*fmaxf(hd,0.f);
        }
}

// ---- K6: single-pass decoupled-lookback scan -> cell (fp16 + fp32) ----
__global__ __launch_bounds__(512) void k_scan(const float* __restrict__ initcx){
    int bc = blockIdx.x; int b = bc>>6; int c = bc&63; int t = threadIdx.x;
    int base = (b*Ss + c*CS)*HD + t;

    float a = 1.f, bv = 0.f;
    #pragma unroll 8
    for (int s=0;s<CS;s++){
        float f = g_fg[base + s*HD];
        float g = g_igh[base + s*HD];
        a *= f; bv = bv*f + g;
    }
    g_a[bc*HD + t] = a; g_bv[bc*HD + t] = bv;
    __threadfence();
    __syncthreads();
    if (t==0) atomicExch(&g_flag[bc], 1);

    float cell = initcx[t];
    if (c > 0){
        if (t < c){
            volatile int* fl = &g_flag[b*64 + t];
            while (*fl == 0) { }
        }
        __syncthreads();
        __threadfence();
        for (int p=0;p<c;p++){
            int idx = (b*64 + p)*HD + t;
            cell = g_a[idx]*cell + g_bv[idx];
        }
    }

    #pragma unroll 4
    for (int s=0;s<CS;s++){
        float f = g_fg[base + s*HD];
        float g = g_igh[base + s*HD];
        cell = f*cell + g;
        g_cell[base+s*HD] = cell;
        g_ch[base+s*HD] = __float2half(cell);
    }
}

// ---- K7: GEMM2 fp16 mma, fused og*cell (cell fp32) ----
__global__ __launch_bounds__(256,4) void k_gemm2(const float* __restrict__ bias,
                                                 float* __restrict__ out){
    __shared__ __half Ah[2][64*24];
    __shared__ __half Bh[2][64*24];
    int t = threadIdx.x;
    int r0 = blockIdx.x*64;
    int lane=t&31, wid=t>>5, wm=wid&1, wn=wid>>1;
    int g=lane>>2, tg=lane&3;

    float Cr[2][2][4];
    #pragma unroll
    for (int a=0;a<2;a++)
        #pragma unroll
        for (int b=0;b<2;b++)
            #pragma unroll
            for (int c=0;c<4;c++) Cr[a][b][c]=0.f;

    unsigned ra[2], rb[2];
    auto load_stage = [&](int s){
        const unsigned* ga = (const unsigned*)(s<4 ? g_xh : g_ch);
        int so = (s&3)*8;
        #pragma unroll
        for (int i=0;i<2;i++){
            int idx = t + i*256, row = idx>>3, c8 = idx&7;
            ra[i] = ga[(r0+row)*32 + so + c8];
        }
        const unsigned* gb = (const unsigned*)g_W2h;
        #pragma unroll
        for (int i=0;i<2;i++){
            int idx = t + i*256, row = idx>>3, c8 = idx&7;
            rb[i] = gb[row*64 + s*8 + c8];
        }
    };
    auto store_stage = [&](int buf){
        unsigned* sa=(unsigned*)Ah[buf];
        unsigned* sbm=(unsigned*)Bh[buf];
        #pragma unroll
        for (int i=0;i<2;i++){
            int idx = t + i*256, row = idx>>3, c8 = idx&7;
            sa[row*12+c8]=ra[i];
            sbm[row*12+c8]=rb[i];
        }
    };

    load_stage(0); store_stage(0); __syncthreads();
    for (int s=0;s<8;s++){
        int buf = s&1;
        if (s<7) load_stage(s+1);
        const unsigned* As=(const unsigned*)Ah[buf];
        const unsigned* Bs=(const unsigned*)Bh[buf];
        unsigned a[2][4];
        #pragma unroll
        for (int mf=0;mf<2;mf++){
            int mr = wm*32 + mf*16;
            a[mf][0]=As[(mr+g  )*12+tg  ]; a[mf][1]=As[(mr+g+8)*12+tg  ];
            a[mf][2]=As[(mr+g  )*12+tg+4]; a[mf][3]=As[(mr+g+8)*12+tg+4];
        }
        #pragma unroll
        for (int nf=0;nf<2;nf++){
            int cb = wn*16 + nf*8 + g;
            unsigned b0=Bs[cb*12+tg], b1=Bs[cb*12+tg+4];
            #pragma unroll
            for (int mf=0;mf<2;mf++)
                mma16(Cr[mf][nf], a[mf], b0, b1);
        }
        if (s<7){ store_stage((s+1)&1); __syncthreads(); }
    }
    #pragma unroll
    for (int mf=0;mf<2;mf++)
        #pragma unroll
        for (int nf=0;nf<2;nf++)
            #pragma unroll
            for (int j=0;j<4;j++){
                int row = r0 + wm*32 + mf*16 + g + ((j>>1)<<3);
                int col = wn*16 + nf*8 + 2*tg + (j&1);
                float og = sigmf(Cr[mf][nf][j] + __ldg(&bias[col]));
                out[row*64+col] = og * g_cell[row*64+col];
            }
}

extern "C" void kernel_launch(void* const* d_in, const int* in_sizes, int n_in,
                              void* d_out, int out_size){
    const float* x      = (const float*)d_in[0];
    const float* W_hid  = (const float*)d_in[1];
    const float* b_hid  = (const float*)d_in[2];
    const float* W_og   = (const float*)d_in[3];
    const float* b_og   = (const float*)d_in[4];
    const float* gamma  = (const float*)d_in[5];
    const float* beta   = (const float*)d_in[6];
    const float* initcx = (const float*)d_in[7];
    float* out = (float*)d_out;

    k_chunksum <<<Bb*NC, 512>>>(x);
    k_chunkscan<<<16, 128>>>();
    k_csum     <<<Bb*NC, 512>>>(x);
    k_ln       <<<BSn/16, 512>>>(gamma, beta);     // captured slot
    k_prepw    <<<256, 128>>>(W_hid, W_og);
    k_gemm1    <<<dim3(Mm/64, 2), 256>>>(b_hid);
    k_scan     <<<Bb*NC, 512>>>(initcx);
    k_gemm2    <<<Mm/64, 256>>>(b_og, out);
}